// round 3
// baseline (speedup 1.0000x reference)
#include <cuda_runtime.h>
#include <math.h>

#define NHEADS 16
#define HDIM   128
#define SEQLEN 2048
#define NBATCH 2
#define HID    2048
#define NBH    (NBATCH*NHEADS)   // 32

// Scratch for projected Q/K/V in [b,h,s,d] layout (32 MB each)
__device__ float g_Q[(size_t)NBH*SEQLEN*HDIM];
__device__ float g_K[(size_t)NBH*SEQLEN*HDIM];
__device__ float g_V[(size_t)NBH*SEQLEN*HDIM];

// ---------------------------------------------------------------------------
// Fused QKV projection: out[m,n] = sum_k X[m,k]*W[n,k] + b[n]
// 128x128 tile, BK=8, 8x8 per thread, 256 threads. blockIdx.z selects Q/K/V.
// Register-prefetch of next K-step's global loads hides LDG latency.
// ---------------------------------------------------------------------------
__global__ __launch_bounds__(256) void qkv_gemm_kernel(
    const float* __restrict__ X,
    const float* __restrict__ Wq, const float* __restrict__ bq,
    const float* __restrict__ Wk, const float* __restrict__ bk,
    const float* __restrict__ Wv, const float* __restrict__ bv)
{
    __shared__ float As[8][128];
    __shared__ float Bs[8][128];

    const float* W; const float* bias; float* dst;
    if (blockIdx.z == 0)      { W = Wq; bias = bq; dst = g_Q; }
    else if (blockIdx.z == 1) { W = Wk; bias = bk; dst = g_K; }
    else                      { W = Wv; bias = bv; dst = g_V; }

    const int tid = threadIdx.x;
    const int m0 = blockIdx.y * 128;
    const int n0 = blockIdx.x * 128;
    const int tr = tid >> 4;        // 0..15
    const int tc = tid & 15;        // 0..15

    const int lr = tid >> 1;        // 0..127 load row
    const int lc = (tid & 1) * 4;   // 0 or 4

    const float* Ap = X + (size_t)(m0 + lr) * HID + lc;
    const float* Bp = W + (size_t)(n0 + lr) * HID + lc;

    float acc[8][8];
    #pragma unroll
    for (int i = 0; i < 8; i++)
        #pragma unroll
        for (int j = 0; j < 8; j++) acc[i][j] = 0.f;

    // prefetch first K-step
    float4 a4 = *(const float4*)(Ap);
    float4 b4 = *(const float4*)(Bp);

    for (int k0 = 0; k0 < HID; k0 += 8) {
        As[lc+0][lr] = a4.x; As[lc+1][lr] = a4.y;
        As[lc+2][lr] = a4.z; As[lc+3][lr] = a4.w;
        Bs[lc+0][lr] = b4.x; Bs[lc+1][lr] = b4.y;
        Bs[lc+2][lr] = b4.z; Bs[lc+3][lr] = b4.w;
        __syncthreads();

        // prefetch next K-step while computing this one
        if (k0 + 8 < HID) {
            a4 = *(const float4*)(Ap + k0 + 8);
            b4 = *(const float4*)(Bp + k0 + 8);
        }

        #pragma unroll
        for (int kk = 0; kk < 8; kk++) {
            float4 a0 = *(const float4*)(&As[kk][tr*8]);
            float4 a1 = *(const float4*)(&As[kk][tr*8+4]);
            float4 b0 = *(const float4*)(&Bs[kk][tc*8]);
            float4 b1 = *(const float4*)(&Bs[kk][tc*8+4]);
            float rm[8] = {a0.x,a0.y,a0.z,a0.w,a1.x,a1.y,a1.z,a1.w};
            float rn[8] = {b0.x,b0.y,b0.z,b0.w,b1.x,b1.y,b1.z,b1.w};
            #pragma unroll
            for (int i = 0; i < 8; i++)
                #pragma unroll
                for (int j = 0; j < 8; j++)
                    acc[i][j] += rm[i] * rn[j];
        }
        __syncthreads();
    }

    // epilogue: +bias, write to [b,h,s,d]
    float rb[8];
    #pragma unroll
    for (int j = 0; j < 8; j++) rb[j] = bias[n0 + tc*8 + j];

    const int n = n0 + tc*8;         // head-aligned: n0 multiple of 128
    const int hh = n >> 7;
    const int dd = n & 127;
    #pragma unroll
    for (int i = 0; i < 8; i++) {
        int m = m0 + tr*8 + i;
        int b = m >> 11;
        int s = m & 2047;
        float* op = dst + (((size_t)(b*NHEADS + hh))*SEQLEN + s)*HDIM + dd;
        float4 o0 = make_float4(acc[i][0]+rb[0], acc[i][1]+rb[1],
                                acc[i][2]+rb[2], acc[i][3]+rb[3]);
        float4 o1 = make_float4(acc[i][4]+rb[4], acc[i][5]+rb[5],
                                acc[i][6]+rb[6], acc[i][7]+rb[7]);
        *(float4*)op       = o0;
        *(float4*)(op + 4) = o1;
    }
}

// ---------------------------------------------------------------------------
// RoPE in-place on g_Q and g_K. One thread per (tensor, bh, s, pair j).
// ---------------------------------------------------------------------------
__global__ __launch_bounds__(256) void rope_kernel()
{
    int idx = blockIdx.x * 256 + threadIdx.x;   // < 2*NBH*SEQLEN*64 = 2^23
    int j  = idx & 63;
    int s  = (idx >> 6) & (SEQLEN - 1);
    int t  = idx >> 17;                         // 0..63
    float* base = (t < NBH) ? g_Q : g_K;
    int bh = t & (NBH - 1);
    float* p = base + ((size_t)bh * SEQLEN + s) * HDIM;

    // inv_freq = 10000^{-j/64} = 2^{-j * log2(10000)/64}
    float inv = exp2f(-(float)j * 0.20762050593046112f);
    float ang = (float)s * inv;
    float sn, cs;
    sincosf(ang, &sn, &cs);
    float x1 = p[j], x2 = p[j + 64];
    p[j]      = x1 * cs - x2 * sn;
    p[j + 64] = x2 * cs + x1 * sn;
}

// ---------------------------------------------------------------------------
// Flash attention: BM=64 queries/block, BN=64 kv/tile, d=128, 256 threads.
// Q,K staged transposed [k][m] in smem (conflict-free LDS.128),
// V row-major padded, P through padded smem. Online softmax with
// 16-lane shuffle reductions (thread grid 16x16: 4 rows x 4 scols / 8 ocols).
// ---------------------------------------------------------------------------
#define ATT_SMEM_FLOATS (128*64 + 128*64 + 64*132 + 64*65)
#define ATT_SMEM_BYTES  (ATT_SMEM_FLOATS * 4)

__global__ __launch_bounds__(256, 1) void attn_kernel(float* __restrict__ out)
{
    extern __shared__ float sm[];
    float* Qs = sm;                  // [128][64]  (k-major)
    float* Ks = Qs + 128*64;         // [128][64]  (k-major)
    float* Vs = Ks + 128*64;         // [64][132]  (row-major, padded)
    float* Ps = Vs + 64*132;         // [64][65]   (padded)

    const int tid = threadIdx.x;
    const int bh  = blockIdx.y;
    const int q0  = blockIdx.x * 64;
    const float* Qg = g_Q + ((size_t)bh * SEQLEN + q0) * HDIM;
    const float* Kg = g_K + (size_t)bh * SEQLEN * HDIM;
    const float* Vg = g_V + (size_t)bh * SEQLEN * HDIM;

    const int ty = tid >> 4, tx = tid & 15;
    const int lrow = tid >> 2;       // 0..63
    const int lcol = tid & 3;        // 0..3

    // Load Q tile transposed into smem
    #pragma unroll
    for (int jj = 0; jj < 8; jj++) {
        int kq = lcol + jj * 4;      // float4 index 0..31
        float4 a = *(const float4*)(Qg + (size_t)lrow * HDIM + kq * 4);
        Qs[(kq*4+0)*64 + lrow] = a.x;
        Qs[(kq*4+1)*64 + lrow] = a.y;
        Qs[(kq*4+2)*64 + lrow] = a.z;
        Qs[(kq*4+3)*64 + lrow] = a.w;
    }

    float mi[4], li[4], acc[4][8];
    #pragma unroll
    for (int i = 0; i < 4; i++) {
        mi[i] = -INFINITY; li[i] = 0.f;
        #pragma unroll
        for (int j = 0; j < 8; j++) acc[i][j] = 0.f;
    }
    __syncthreads();

    const float scale = 0.08838834764831844f;   // 1/sqrt(128)

    for (int n0 = 0; n0 < SEQLEN; n0 += 64) {
        // Load K (transposed) and V tiles
        #pragma unroll
        for (int jj = 0; jj < 8; jj++) {
            int kq = lcol + jj * 4;
            float4 a = *(const float4*)(Kg + ((size_t)(n0 + lrow)) * HDIM + kq * 4);
            Ks[(kq*4+0)*64 + lrow] = a.x;
            Ks[(kq*4+1)*64 + lrow] = a.y;
            Ks[(kq*4+2)*64 + lrow] = a.z;
            Ks[(kq*4+3)*64 + lrow] = a.w;
            float4 v = *(const float4*)(Vg + ((size_t)(n0 + lrow)) * HDIM + kq * 4);
            *(float4*)(Vs + lrow*132 + kq*4) = v;
        }
        __syncthreads();

        // S = Q K^T (4x4 per thread)
        float sv[4][4];
        #pragma unroll
        for (int i = 0; i < 4; i++)
            #pragma unroll
            for (int j = 0; j < 4; j++) sv[i][j] = 0.f;

        #pragma unroll 8
        for (int k = 0; k < HDIM; k++) {
            float4 q  = *(const float4*)(Qs + k*64 + ty*4);
            float4 kv = *(const float4*)(Ks + k*64 + tx*4);
            float qa[4] = {q.x, q.y, q.z, q.w};
            float ka[4] = {kv.x, kv.y, kv.z, kv.w};
            #pragma unroll
            for (int i = 0; i < 4; i++)
                #pragma unroll
                for (int j = 0; j < 4; j++)
                    sv[i][j] += qa[i] * ka[j];
        }

        // online softmax update (state replicated across the 16 lanes of a row group)
        #pragma unroll
        for (int i = 0; i < 4; i++) {
            float r = fmaxf(fmaxf(sv[i][0], sv[i][1]), fmaxf(sv[i][2], sv[i][3])) * scale;
            r = fmaxf(r, __shfl_xor_sync(0xffffffffu, r, 8));
            r = fmaxf(r, __shfl_xor_sync(0xffffffffu, r, 4));
            r = fmaxf(r, __shfl_xor_sync(0xffffffffu, r, 2));
            r = fmaxf(r, __shfl_xor_sync(0xffffffffu, r, 1));
            float nm = fmaxf(mi[i], r);
            float f  = __expf(mi[i] - nm);
            mi[i] = nm;
            float rs = 0.f;
            #pragma unroll
            for (int j = 0; j < 4; j++) {
                float p = __expf(sv[i][j] * scale - nm);
                Ps[(ty*4+i)*65 + tx*4 + j] = p;
                rs += p;
            }
            rs += __shfl_xor_sync(0xffffffffu, rs, 8);
            rs += __shfl_xor_sync(0xffffffffu, rs, 4);
            rs += __shfl_xor_sync(0xffffffffu, rs, 2);
            rs += __shfl_xor_sync(0xffffffffu, rs, 1);
            li[i] = li[i] * f + rs;
            #pragma unroll
            for (int j = 0; j < 8; j++) acc[i][j] *= f;
        }
        __syncthreads();

        // acc += P @ V   (rows ty*4+i, out cols tx*8..tx*8+7)
        #pragma unroll 4
        for (int n = 0; n < 64; n++) {
            float4 v0 = *(const float4*)(Vs + n*132 + tx*8);
            float4 v1 = *(const float4*)(Vs + n*132 + tx*8 + 4);
            #pragma unroll
            for (int i = 0; i < 4; i++) {
                float p = Ps[(ty*4+i)*65 + n];
                acc[i][0] += p * v0.x; acc[i][1] += p * v0.y;
                acc[i][2] += p * v0.z; acc[i][3] += p * v0.w;
                acc[i][4] += p * v1.x; acc[i][5] += p * v1.y;
                acc[i][6] += p * v1.z; acc[i][7] += p * v1.w;
            }
        }
        __syncthreads();
    }

    // epilogue: out[b, s, hh*128 + d] = acc / l
    const int b  = bh >> 4;
    const int hh = bh & 15;
    #pragma unroll
    for (int i = 0; i < 4; i++) {
        int s = q0 + ty*4 + i;
        float inv = 1.0f / li[i];
        float* op = out + ((size_t)(b * SEQLEN + s)) * HID + hh * HDIM + tx * 8;
        float4 o0 = make_float4(acc[i][0]*inv, acc[i][1]*inv, acc[i][2]*inv, acc[i][3]*inv);
        float4 o1 = make_float4(acc[i][4]*inv, acc[i][5]*inv, acc[i][6]*inv, acc[i][7]*inv);
        *(float4*)op       = o0;
        *(float4*)(op + 4) = o1;
    }
}

// ---------------------------------------------------------------------------
extern "C" void kernel_launch(void* const* d_in, const int* in_sizes, int n_in,
                              void* d_out, int out_size)
{
    const float* X  = (const float*)d_in[0];
    const float* Wq = (const float*)d_in[1];
    const float* bq = (const float*)d_in[2];
    const float* Wk = (const float*)d_in[3];
    const float* bk = (const float*)d_in[4];
    const float* Wv = (const float*)d_in[5];
    const float* bv = (const float*)d_in[6];
    float* out = (float*)d_out;

    // Opt-in to >48KB dynamic smem for the attention kernel. Non-stream API:
    // capture-legal. Tolerate (ignore) a non-success return so a spurious
    // error can never poison the capture.
    (void)cudaFuncSetAttribute(attn_kernel,
                               cudaFuncAttributeMaxDynamicSharedMemorySize,
                               ATT_SMEM_BYTES);

    dim3 gemm_grid(HID/128, (NBATCH*SEQLEN)/128, 3);   // 16 x 32 x 3
    qkv_gemm_kernel<<<gemm_grid, 256>>>(X, Wq, bq, Wk, bk, Wv, bv);

    int rope_threads_total = 2 * NBH * SEQLEN * 64;     // 2^23
    rope_kernel<<<rope_threads_total / 256, 256>>>();

    dim3 attn_grid(SEQLEN/64, NBH);                     // 32 x 32
    attn_kernel<<<attn_grid, 256, ATT_SMEM_BYTES>>>(out);
}

// round 6
// speedup vs baseline: 1.5950x; 1.5950x over previous
#include <cuda_runtime.h>
#include <math.h>
#include <stdint.h>

#define NHEADS 16
#define HDIM   128
#define SEQLEN 2048
#define NBATCH 2
#define HID    2048
#define NBH    (NBATCH*NHEADS)   // 32
#define MROWS  (NBATCH*SEQLEN)   // 4096

// Scratch for projected Q/K/V in [b,h,s,d] layout (32 MB each)
__device__ float g_Q[(size_t)NBH*SEQLEN*HDIM];
__device__ float g_K[(size_t)NBH*SEQLEN*HDIM];
__device__ float g_V[(size_t)NBH*SEQLEN*HDIM];

__device__ __forceinline__ uint32_t f2tf32(float f) {
    uint32_t r;
    asm("cvt.rna.tf32.f32 %0, %1;" : "=r"(r) : "f"(f));
    return r;
}

__device__ __forceinline__ void mma1688(float* d, const uint32_t* a, const uint32_t* b) {
    asm volatile(
        "mma.sync.aligned.m16n8k8.row.col.f32.tf32.tf32.f32 "
        "{%0,%1,%2,%3}, {%4,%5,%6,%7}, {%8,%9}, {%0,%1,%2,%3};"
        : "+f"(d[0]), "+f"(d[1]), "+f"(d[2]), "+f"(d[3])
        : "r"(a[0]), "r"(a[1]), "r"(a[2]), "r"(a[3]), "r"(b[0]), "r"(b[1]));
}

// ===========================================================================
// QKV projection via tf32 mma.sync: out[m,n] = sum_k X[m,k]*W[n,k] + b[n]
// 128x128 CTA tile, 8 warps (2x4), 64x32 per warp, BK=32, double-buffered.
// smem layout: [row][k] with stride 36 (conflict-free fragment loads).
// blockIdx.z selects Q/K/V. Inputs RN-rounded to tf32 at staging.
// ===========================================================================
#define GK_PAD    36
#define GK_BUF    (128*GK_PAD)          // floats per operand per stage
#define GK_SMEM_DYN (4*GK_BUF*4)        // 2 ops x 2 stages = 73728 B

__global__ __launch_bounds__(256) void qkv_mma_kernel(
    const float* __restrict__ X,
    const float* __restrict__ Wq, const float* __restrict__ bq,
    const float* __restrict__ Wk, const float* __restrict__ bk,
    const float* __restrict__ Wv, const float* __restrict__ bv)
{
    extern __shared__ float gsm[];
    float* sA = gsm;                    // [2][GK_BUF]
    float* sB = gsm + 2*GK_BUF;         // [2][GK_BUF]

    const float* W; const float* bias; float* dst;
    if (blockIdx.z == 0)      { W = Wq; bias = bq; dst = g_Q; }
    else if (blockIdx.z == 1) { W = Wk; bias = bk; dst = g_K; }
    else                      { W = Wv; bias = bv; dst = g_V; }

    const int tid  = threadIdx.x;
    const int w    = tid >> 5;
    const int lane = tid & 31;
    const int g    = lane >> 2;         // 0..7
    const int cc   = lane & 3;          // 0..3
    const int wm0  = (w >> 2) * 64;     // warp row offset in tile
    const int wn0  = (w & 3) * 32;      // warp col offset in tile

    const int m0 = blockIdx.y * 128;
    const int n0 = blockIdx.x * 128;

    // global load mapping: 256 threads, 4 passes of 32 rows, 8 float4/row
    const int lrow = tid >> 3;          // 0..31 (+32*pass)
    const int lc4  = tid & 7;           // float4 col

    const float* Ap = X + (size_t)(m0 + lrow) * HID + lc4 * 4;
    const float* Bp = W + (size_t)(n0 + lrow) * HID + lc4 * 4;

    float acc[4][4][4];
    #pragma unroll
    for (int i = 0; i < 4; i++)
        #pragma unroll
        for (int j = 0; j < 4; j++)
            #pragma unroll
            for (int r = 0; r < 4; r++) acc[i][j][r] = 0.f;

    float4 pa[4], pb[4];

    // preload chunk 0
    #pragma unroll
    for (int p = 0; p < 4; p++) {
        pa[p] = *(const float4*)(Ap + (size_t)(p*32) * HID);
        pb[p] = *(const float4*)(Bp + (size_t)(p*32) * HID);
    }
    #pragma unroll
    for (int p = 0; p < 4; p++) {
        uint4 ta = make_uint4(f2tf32(pa[p].x), f2tf32(pa[p].y), f2tf32(pa[p].z), f2tf32(pa[p].w));
        uint4 tb = make_uint4(f2tf32(pb[p].x), f2tf32(pb[p].y), f2tf32(pb[p].z), f2tf32(pb[p].w));
        *(uint4*)(sA + (lrow + p*32)*GK_PAD + lc4*4) = ta;
        *(uint4*)(sB + (lrow + p*32)*GK_PAD + lc4*4) = tb;
    }
    __syncthreads();

    for (int c = 0; c < HID/32; c++) {          // 64 chunks
        const int cur = c & 1;

        if (c < HID/32 - 1) {                   // prefetch next chunk
            const int k0 = (c + 1) * 32;
            #pragma unroll
            for (int p = 0; p < 4; p++) {
                pa[p] = *(const float4*)(Ap + (size_t)(p*32) * HID + k0);
                pb[p] = *(const float4*)(Bp + (size_t)(p*32) * HID + k0);
            }
        }

        const float* A0 = sA + cur * GK_BUF;
        const float* B0 = sB + cur * GK_BUF;
        #pragma unroll
        for (int ks = 0; ks < 32; ks += 8) {
            uint32_t af[4][4], bf[4][2];
            #pragma unroll
            for (int mt = 0; mt < 4; mt++) {
                const float* ap = A0 + (wm0 + mt*16 + g)*GK_PAD + ks + cc;
                af[mt][0] = __float_as_uint(ap[0]);
                af[mt][1] = __float_as_uint(ap[8*GK_PAD]);
                af[mt][2] = __float_as_uint(ap[4]);
                af[mt][3] = __float_as_uint(ap[8*GK_PAD + 4]);
            }
            #pragma unroll
            for (int nt = 0; nt < 4; nt++) {
                const float* bp = B0 + (wn0 + nt*8 + g)*GK_PAD + ks + cc;
                bf[nt][0] = __float_as_uint(bp[0]);
                bf[nt][1] = __float_as_uint(bp[4]);
            }
            #pragma unroll
            for (int mt = 0; mt < 4; mt++)
                #pragma unroll
                for (int nt = 0; nt < 4; nt++)
                    mma1688(acc[mt][nt], af[mt], bf[nt]);
        }

        if (c < HID/32 - 1) {
            float* An = sA + ((c+1) & 1) * GK_BUF;
            float* Bn = sB + ((c+1) & 1) * GK_BUF;
            #pragma unroll
            for (int p = 0; p < 4; p++) {
                uint4 ta = make_uint4(f2tf32(pa[p].x), f2tf32(pa[p].y), f2tf32(pa[p].z), f2tf32(pa[p].w));
                uint4 tb = make_uint4(f2tf32(pb[p].x), f2tf32(pb[p].y), f2tf32(pb[p].z), f2tf32(pb[p].w));
                *(uint4*)(An + (lrow + p*32)*GK_PAD + lc4*4) = ta;
                *(uint4*)(Bn + (lrow + p*32)*GK_PAD + lc4*4) = tb;
            }
        }
        __syncthreads();
    }

    // epilogue: c-frag (m = g or g+8, n = cc*2, cc*2+1) + bias, scatter to [b,h,s,d]
    #pragma unroll
    for (int mt = 0; mt < 4; mt++) {
        #pragma unroll
        for (int half = 0; half < 2; half++) {
            const int m = m0 + wm0 + mt*16 + g + half*8;
            const int b = m >> 11;
            const int s = m & (SEQLEN - 1);
            #pragma unroll
            for (int nt = 0; nt < 4; nt++) {
                const int n  = n0 + wn0 + nt*8 + cc*2;
                const int hh = n >> 7;
                const int dd = n & 127;
                float* op = dst + (((size_t)(b*NHEADS + hh))*SEQLEN + s)*HDIM + dd;
                float2 o;
                o.x = acc[mt][nt][half*2 + 0] + bias[n];
                o.y = acc[mt][nt][half*2 + 1] + bias[n + 1];
                *(float2*)op = o;
            }
        }
    }
}

// ---------------------------------------------------------------------------
// RoPE in-place on g_Q and g_K. One thread per (tensor, bh, s, pair j).
// ---------------------------------------------------------------------------
__global__ __launch_bounds__(256) void rope_kernel()
{
    int idx = blockIdx.x * 256 + threadIdx.x;   // < 2*NBH*SEQLEN*64 = 2^23
    int j  = idx & 63;
    int s  = (idx >> 6) & (SEQLEN - 1);
    int t  = idx >> 17;                         // 0..63
    float* base = (t < NBH) ? g_Q : g_K;
    int bh = t & (NBH - 1);
    float* p = base + ((size_t)bh * SEQLEN + s) * HDIM;

    float inv = exp2f(-(float)j * 0.20762050593046112f);
    float ang = (float)s * inv;
    float sn, cs;
    sincosf(ang, &sn, &cs);
    float x1 = p[j], x2 = p[j + 64];
    p[j]      = x1 * cs - x2 * sn;
    p[j + 64] = x2 * cs + x1 * sn;
}

// ---------------------------------------------------------------------------
// Flash attention (fp32 SIMT, unchanged from passing round-3 kernel)
// ---------------------------------------------------------------------------
#define ATT_SMEM_FLOATS (128*64 + 128*64 + 64*132 + 64*65)
#define ATT_SMEM_BYTES  (ATT_SMEM_FLOATS * 4)

__global__ __launch_bounds__(256, 1) void attn_kernel(float* __restrict__ out)
{
    extern __shared__ float sm[];
    float* Qs = sm;                  // [128][64]  (k-major)
    float* Ks = Qs + 128*64;         // [128][64]  (k-major)
    float* Vs = Ks + 128*64;         // [64][132]  (row-major, padded)
    float* Ps = Vs + 64*132;         // [64][65]   (padded)

    const int tid = threadIdx.x;
    const int bh  = blockIdx.y;
    const int q0  = blockIdx.x * 64;
    const float* Qg = g_Q + ((size_t)bh * SEQLEN + q0) * HDIM;
    const float* Kg = g_K + (size_t)bh * SEQLEN * HDIM;
    const float* Vg = g_V + (size_t)bh * SEQLEN * HDIM;

    const int ty = tid >> 4, tx = tid & 15;
    const int lrow = tid >> 2;       // 0..63
    const int lcol = tid & 3;        // 0..3

    #pragma unroll
    for (int jj = 0; jj < 8; jj++) {
        int kq = lcol + jj * 4;
        float4 a = *(const float4*)(Qg + (size_t)lrow * HDIM + kq * 4);
        Qs[(kq*4+0)*64 + lrow] = a.x;
        Qs[(kq*4+1)*64 + lrow] = a.y;
        Qs[(kq*4+2)*64 + lrow] = a.z;
        Qs[(kq*4+3)*64 + lrow] = a.w;
    }

    float mi[4], li[4], acc[4][8];
    #pragma unroll
    for (int i = 0; i < 4; i++) {
        mi[i] = -INFINITY; li[i] = 0.f;
        #pragma unroll
        for (int j = 0; j < 8; j++) acc[i][j] = 0.f;
    }
    __syncthreads();

    const float scale = 0.08838834764831844f;   // 1/sqrt(128)

    for (int n0 = 0; n0 < SEQLEN; n0 += 64) {
        #pragma unroll
        for (int jj = 0; jj < 8; jj++) {
            int kq = lcol + jj * 4;
            float4 a = *(const float4*)(Kg + ((size_t)(n0 + lrow)) * HDIM + kq * 4);
            Ks[(kq*4+0)*64 + lrow] = a.x;
            Ks[(kq*4+1)*64 + lrow] = a.y;
            Ks[(kq*4+2)*64 + lrow] = a.z;
            Ks[(kq*4+3)*64 + lrow] = a.w;
            float4 v = *(const float4*)(Vg + ((size_t)(n0 + lrow)) * HDIM + kq * 4);
            *(float4*)(Vs + lrow*132 + kq*4) = v;
        }
        __syncthreads();

        float sv[4][4];
        #pragma unroll
        for (int i = 0; i < 4; i++)
            #pragma unroll
            for (int j = 0; j < 4; j++) sv[i][j] = 0.f;

        #pragma unroll 8
        for (int k = 0; k < HDIM; k++) {
            float4 q  = *(const float4*)(Qs + k*64 + ty*4);
            float4 kv = *(const float4*)(Ks + k*64 + tx*4);
            float qa[4] = {q.x, q.y, q.z, q.w};
            float ka[4] = {kv.x, kv.y, kv.z, kv.w};
            #pragma unroll
            for (int i = 0; i < 4; i++)
                #pragma unroll
                for (int j = 0; j < 4; j++)
                    sv[i][j] += qa[i] * ka[j];
        }

        #pragma unroll
        for (int i = 0; i < 4; i++) {
            float r = fmaxf(fmaxf(sv[i][0], sv[i][1]), fmaxf(sv[i][2], sv[i][3])) * scale;
            r = fmaxf(r, __shfl_xor_sync(0xffffffffu, r, 8));
            r = fmaxf(r, __shfl_xor_sync(0xffffffffu, r, 4));
            r = fmaxf(r, __shfl_xor_sync(0xffffffffu, r, 2));
            r = fmaxf(r, __shfl_xor_sync(0xffffffffu, r, 1));
            float nm = fmaxf(mi[i], r);
            float f  = __expf(mi[i] - nm);
            mi[i] = nm;
            float rs = 0.f;
            #pragma unroll
            for (int j = 0; j < 4; j++) {
                float p = __expf(sv[i][j] * scale - nm);
                Ps[(ty*4+i)*65 + tx*4 + j] = p;
                rs += p;
            }
            rs += __shfl_xor_sync(0xffffffffu, rs, 8);
            rs += __shfl_xor_sync(0xffffffffu, rs, 4);
            rs += __shfl_xor_sync(0xffffffffu, rs, 2);
            rs += __shfl_xor_sync(0xffffffffu, rs, 1);
            li[i] = li[i] * f + rs;
            #pragma unroll
            for (int j = 0; j < 8; j++) acc[i][j] *= f;
        }
        __syncthreads();

        #pragma unroll 4
        for (int n = 0; n < 64; n++) {
            float4 v0 = *(const float4*)(Vs + n*132 + tx*8);
            float4 v1 = *(const float4*)(Vs + n*132 + tx*8 + 4);
            #pragma unroll
            for (int i = 0; i < 4; i++) {
                float p = Ps[(ty*4+i)*65 + n];
                acc[i][0] += p * v0.x; acc[i][1] += p * v0.y;
                acc[i][2] += p * v0.z; acc[i][3] += p * v0.w;
                acc[i][4] += p * v1.x; acc[i][5] += p * v1.y;
                acc[i][6] += p * v1.z; acc[i][7] += p * v1.w;
            }
        }
        __syncthreads();
    }

    const int b  = bh >> 4;
    const int hh = bh & 15;
    #pragma unroll
    for (int i = 0; i < 4; i++) {
        int s = q0 + ty*4 + i;
        float inv = 1.0f / li[i];
        float* op = out + ((size_t)(b * SEQLEN + s)) * HID + hh * HDIM + tx * 8;
        float4 o0 = make_float4(acc[i][0]*inv, acc[i][1]*inv, acc[i][2]*inv, acc[i][3]*inv);
        float4 o1 = make_float4(acc[i][4]*inv, acc[i][5]*inv, acc[i][6]*inv, acc[i][7]*inv);
        *(float4*)op       = o0;
        *(float4*)(op + 4) = o1;
    }
}

// ---------------------------------------------------------------------------
extern "C" void kernel_launch(void* const* d_in, const int* in_sizes, int n_in,
                              void* d_out, int out_size)
{
    const float* X  = (const float*)d_in[0];
    const float* Wq = (const float*)d_in[1];
    const float* bq = (const float*)d_in[2];
    const float* Wk = (const float*)d_in[3];
    const float* bk = (const float*)d_in[4];
    const float* Wv = (const float*)d_in[5];
    const float* bv = (const float*)d_in[6];
    float* out = (float*)d_out;

    (void)cudaFuncSetAttribute(qkv_mma_kernel,
                               cudaFuncAttributeMaxDynamicSharedMemorySize,
                               GK_SMEM_DYN);
    (void)cudaFuncSetAttribute(attn_kernel,
                               cudaFuncAttributeMaxDynamicSharedMemorySize,
                               ATT_SMEM_BYTES);

    dim3 gemm_grid(HID/128, MROWS/128, 3);              // 16 x 32 x 3
    qkv_mma_kernel<<<gemm_grid, 256, GK_SMEM_DYN>>>(X, Wq, bq, Wk, bk, Wv, bv);

    int rope_threads_total = 2 * NBH * SEQLEN * 64;     // 2^23
    rope_kernel<<<rope_threads_total / 256, 256>>>();

    dim3 attn_grid(SEQLEN/64, NBH);                     // 32 x 32
    attn_kernel<<<attn_grid, 256, ATT_SMEM_BYTES>>>(out);
}

// round 7
// speedup vs baseline: 3.2000x; 2.0063x over previous
#include <cuda_runtime.h>
#include <math.h>
#include <stdint.h>

#define NHEADS 16
#define HDIM   128
#define SEQLEN 2048
#define NBATCH 2
#define HID    2048
#define NBH    (NBATCH*NHEADS)   // 32
#define MROWS  (NBATCH*SEQLEN)   // 4096

// Scratch for projected Q/K/V in [b,h,s,d] layout (32 MB each)
__device__ float g_Q[(size_t)NBH*SEQLEN*HDIM];
__device__ float g_K[(size_t)NBH*SEQLEN*HDIM];
__device__ float g_V[(size_t)NBH*SEQLEN*HDIM];

__device__ __forceinline__ uint32_t f2tf32(float f) {
    uint32_t r;
    asm("cvt.rna.tf32.f32 %0, %1;" : "=r"(r) : "f"(f));
    return r;
}

__device__ __forceinline__ void mma1688(float* d, const uint32_t* a, const uint32_t* b) {
    asm volatile(
        "mma.sync.aligned.m16n8k8.row.col.f32.tf32.tf32.f32 "
        "{%0,%1,%2,%3}, {%4,%5,%6,%7}, {%8,%9}, {%0,%1,%2,%3};"
        : "+f"(d[0]), "+f"(d[1]), "+f"(d[2]), "+f"(d[3])
        : "r"(a[0]), "r"(a[1]), "r"(a[2]), "r"(a[3]), "r"(b[0]), "r"(b[1]));
}

// ===========================================================================
// QKV projection via tf32 mma.sync (unchanged from round-6 passing kernel)
// ===========================================================================
#define GK_PAD    36
#define GK_BUF    (128*GK_PAD)
#define GK_SMEM_DYN (4*GK_BUF*4)

__global__ __launch_bounds__(256) void qkv_mma_kernel(
    const float* __restrict__ X,
    const float* __restrict__ Wq, const float* __restrict__ bq,
    const float* __restrict__ Wk, const float* __restrict__ bk,
    const float* __restrict__ Wv, const float* __restrict__ bv)
{
    extern __shared__ float gsm[];
    float* sA = gsm;
    float* sB = gsm + 2*GK_BUF;

    const float* W; const float* bias; float* dst;
    if (blockIdx.z == 0)      { W = Wq; bias = bq; dst = g_Q; }
    else if (blockIdx.z == 1) { W = Wk; bias = bk; dst = g_K; }
    else                      { W = Wv; bias = bv; dst = g_V; }

    const int tid  = threadIdx.x;
    const int w    = tid >> 5;
    const int lane = tid & 31;
    const int g    = lane >> 2;
    const int cc   = lane & 3;
    const int wm0  = (w >> 2) * 64;
    const int wn0  = (w & 3) * 32;

    const int m0 = blockIdx.y * 128;
    const int n0 = blockIdx.x * 128;

    const int lrow = tid >> 3;
    const int lc4  = tid & 7;

    const float* Ap = X + (size_t)(m0 + lrow) * HID + lc4 * 4;
    const float* Bp = W + (size_t)(n0 + lrow) * HID + lc4 * 4;

    float acc[4][4][4];
    #pragma unroll
    for (int i = 0; i < 4; i++)
        #pragma unroll
        for (int j = 0; j < 4; j++)
            #pragma unroll
            for (int r = 0; r < 4; r++) acc[i][j][r] = 0.f;

    float4 pa[4], pb[4];

    #pragma unroll
    for (int p = 0; p < 4; p++) {
        pa[p] = *(const float4*)(Ap + (size_t)(p*32) * HID);
        pb[p] = *(const float4*)(Bp + (size_t)(p*32) * HID);
    }
    #pragma unroll
    for (int p = 0; p < 4; p++) {
        uint4 ta = make_uint4(f2tf32(pa[p].x), f2tf32(pa[p].y), f2tf32(pa[p].z), f2tf32(pa[p].w));
        uint4 tb = make_uint4(f2tf32(pb[p].x), f2tf32(pb[p].y), f2tf32(pb[p].z), f2tf32(pb[p].w));
        *(uint4*)(sA + (lrow + p*32)*GK_PAD + lc4*4) = ta;
        *(uint4*)(sB + (lrow + p*32)*GK_PAD + lc4*4) = tb;
    }
    __syncthreads();

    for (int c = 0; c < HID/32; c++) {
        const int cur = c & 1;

        if (c < HID/32 - 1) {
            const int k0 = (c + 1) * 32;
            #pragma unroll
            for (int p = 0; p < 4; p++) {
                pa[p] = *(const float4*)(Ap + (size_t)(p*32) * HID + k0);
                pb[p] = *(const float4*)(Bp + (size_t)(p*32) * HID + k0);
            }
        }

        const float* A0 = sA + cur * GK_BUF;
        const float* B0 = sB + cur * GK_BUF;
        #pragma unroll
        for (int ks = 0; ks < 32; ks += 8) {
            uint32_t af[4][4], bf[4][2];
            #pragma unroll
            for (int mt = 0; mt < 4; mt++) {
                const float* ap = A0 + (wm0 + mt*16 + g)*GK_PAD + ks + cc;
                af[mt][0] = __float_as_uint(ap[0]);
                af[mt][1] = __float_as_uint(ap[8*GK_PAD]);
                af[mt][2] = __float_as_uint(ap[4]);
                af[mt][3] = __float_as_uint(ap[8*GK_PAD + 4]);
            }
            #pragma unroll
            for (int nt = 0; nt < 4; nt++) {
                const float* bp = B0 + (wn0 + nt*8 + g)*GK_PAD + ks + cc;
                bf[nt][0] = __float_as_uint(bp[0]);
                bf[nt][1] = __float_as_uint(bp[4]);
            }
            #pragma unroll
            for (int mt = 0; mt < 4; mt++)
                #pragma unroll
                for (int nt = 0; nt < 4; nt++)
                    mma1688(acc[mt][nt], af[mt], bf[nt]);
        }

        if (c < HID/32 - 1) {
            float* An = sA + ((c+1) & 1) * GK_BUF;
            float* Bn = sB + ((c+1) & 1) * GK_BUF;
            #pragma unroll
            for (int p = 0; p < 4; p++) {
                uint4 ta = make_uint4(f2tf32(pa[p].x), f2tf32(pa[p].y), f2tf32(pa[p].z), f2tf32(pa[p].w));
                uint4 tb = make_uint4(f2tf32(pb[p].x), f2tf32(pb[p].y), f2tf32(pb[p].z), f2tf32(pb[p].w));
                *(uint4*)(An + (lrow + p*32)*GK_PAD + lc4*4) = ta;
                *(uint4*)(Bn + (lrow + p*32)*GK_PAD + lc4*4) = tb;
            }
        }
        __syncthreads();
    }

    #pragma unroll
    for (int mt = 0; mt < 4; mt++) {
        #pragma unroll
        for (int half = 0; half < 2; half++) {
            const int m = m0 + wm0 + mt*16 + g + half*8;
            const int b = m >> 11;
            const int s = m & (SEQLEN - 1);
            #pragma unroll
            for (int nt = 0; nt < 4; nt++) {
                const int n  = n0 + wn0 + nt*8 + cc*2;
                const int hh = n >> 7;
                const int dd = n & 127;
                float* op = dst + (((size_t)(b*NHEADS + hh))*SEQLEN + s)*HDIM + dd;
                float2 o;
                o.x = acc[mt][nt][half*2 + 0] + bias[n];
                o.y = acc[mt][nt][half*2 + 1] + bias[n + 1];
                *(float2*)op = o;
            }
        }
    }
}

// ---------------------------------------------------------------------------
// RoPE in-place on g_Q and g_K.
// ---------------------------------------------------------------------------
__global__ __launch_bounds__(256) void rope_kernel()
{
    int idx = blockIdx.x * 256 + threadIdx.x;
    int j  = idx & 63;
    int s  = (idx >> 6) & (SEQLEN - 1);
    int t  = idx >> 17;
    float* base = (t < NBH) ? g_Q : g_K;
    int bh = t & (NBH - 1);
    float* p = base + ((size_t)bh * SEQLEN + s) * HDIM;

    float inv = exp2f(-(float)j * 0.20762050593046112f);
    float ang = (float)s * inv;
    float sn, cs;
    sincosf(ang, &sn, &cs);
    float x1 = p[j], x2 = p[j + 64];
    p[j]      = x1 * cs - x2 * sn;
    p[j + 64] = x2 * cs + x1 * sn;
}

// ===========================================================================
// Flash attention via tf32 mma.sync.
// BM=128 queries/CTA (8 warps x 16 rows), BN=64 kv/tile, d=128.
// Q tf32 in smem (pad 132); per tile: K tf32 (pad 132), V^T tf32 [d][kv]
// (pad 68). S = Q K^T -> online softmax in c-frags (quad shuffles) ->
// P tf32 to smem (warp-private rows, pad 68) -> O += P V^T.
// ===========================================================================
#define AQ_PAD 132
#define AK_PAD 132
#define AV_PAD 68
#define AP_PAD 68
#define AT_QS  (128*AQ_PAD)
#define AT_KS  (64*AK_PAD)
#define AT_VT  (128*AV_PAD)
#define AT_PS  (128*AP_PAD)
#define ATT2_SMEM ((AT_QS + AT_KS + AT_VT + AT_PS) * 4)   // 171008 B

__global__ __launch_bounds__(256, 1) void attn_mma_kernel(float* __restrict__ out)
{
    extern __shared__ float sm[];
    float* Qs = sm;                   // [128][132] tf32
    float* Ks = Qs + AT_QS;           // [64][132]  tf32
    float* Vt = Ks + AT_KS;           // [128][68]  tf32 (V transposed: [d][kv])
    float* Ps = Vt + AT_VT;           // [128][68]  tf32

    const int tid  = threadIdx.x;
    const int w    = tid >> 5;
    const int lane = tid & 31;
    const int g    = lane >> 2;       // 0..7
    const int cc   = lane & 3;        // 0..3
    const int wm   = w * 16;          // warp's query-row base in tile

    const int bh = blockIdx.y;
    const int q0 = blockIdx.x * 128;
    const float* Qg = g_Q + ((size_t)bh * SEQLEN + q0) * HDIM;
    const float* Kg = g_K + (size_t)bh * SEQLEN * HDIM;
    const float* Vg = g_V + (size_t)bh * SEQLEN * HDIM;

    // ---- stage Q (tf32) ----
    {
        const int row  = tid >> 1;          // 0..127
        const int half = tid & 1;
        #pragma unroll
        for (int j = 0; j < 16; j++) {
            const int c4 = half * 16 + j;   // 0..31
            float4 v = *(const float4*)(Qg + (size_t)row * HDIM + c4 * 4);
            uint4 t = make_uint4(f2tf32(v.x), f2tf32(v.y), f2tf32(v.z), f2tf32(v.w));
            *(uint4*)(Qs + row * AQ_PAD + c4 * 4) = t;
        }
    }

    float o[16][4];
    #pragma unroll
    for (int i = 0; i < 16; i++)
        #pragma unroll
        for (int r = 0; r < 4; r++) o[i][r] = 0.f;
    float mi0 = -INFINITY, mi1 = -INFINITY, li0 = 0.f, li1 = 0.f;

    const float scale = 0.08838834764831844f;   // 1/sqrt(128)

    const int krow = tid >> 2;        // 0..63
    const int kq4  = tid & 3;

    __syncthreads();

    for (int n0 = 0; n0 < SEQLEN; n0 += 64) {
        // ---- stage K (tf32) and V^T (tf32) ----
        #pragma unroll
        for (int j = 0; j < 8; j++) {
            const int c4 = kq4 * 8 + j;     // 0..31
            float4 v = *(const float4*)(Kg + (size_t)(n0 + krow) * HDIM + c4 * 4);
            uint4 t = make_uint4(f2tf32(v.x), f2tf32(v.y), f2tf32(v.z), f2tf32(v.w));
            *(uint4*)(Ks + krow * AK_PAD + c4 * 4) = t;

            const int kc4 = kq4 + j * 4;    // 0..31
            float4 vv = *(const float4*)(Vg + (size_t)(n0 + krow) * HDIM + kc4 * 4);
            Vt[(kc4*4+0)*AV_PAD + krow] = __uint_as_float(f2tf32(vv.x));
            Vt[(kc4*4+1)*AV_PAD + krow] = __uint_as_float(f2tf32(vv.y));
            Vt[(kc4*4+2)*AV_PAD + krow] = __uint_as_float(f2tf32(vv.z));
            Vt[(kc4*4+3)*AV_PAD + krow] = __uint_as_float(f2tf32(vv.w));
        }
        __syncthreads();

        // ---- S = Q K^T (warp: 16 x 64) ----
        float s[8][4];
        #pragma unroll
        for (int nt = 0; nt < 8; nt++)
            #pragma unroll
            for (int r = 0; r < 4; r++) s[nt][r] = 0.f;

        #pragma unroll
        for (int ks = 0; ks < 16; ks++) {
            uint32_t a[4];
            const float* ap = Qs + (wm + g) * AQ_PAD + ks * 8 + cc;
            a[0] = __float_as_uint(ap[0]);
            a[1] = __float_as_uint(ap[8*AQ_PAD]);
            a[2] = __float_as_uint(ap[4]);
            a[3] = __float_as_uint(ap[8*AQ_PAD + 4]);
            #pragma unroll
            for (int nt = 0; nt < 8; nt++) {
                uint32_t b[2];
                const float* bp = Ks + (nt*8 + g) * AK_PAD + ks * 8 + cc;
                b[0] = __float_as_uint(bp[0]);
                b[1] = __float_as_uint(bp[4]);
                mma1688(s[nt], a, b);
            }
        }

        // ---- online softmax (rows g and g+8 of warp tile) ----
        float rmax0 = -INFINITY, rmax1 = -INFINITY;
        #pragma unroll
        for (int nt = 0; nt < 8; nt++) {
            rmax0 = fmaxf(rmax0, fmaxf(s[nt][0], s[nt][1]));
            rmax1 = fmaxf(rmax1, fmaxf(s[nt][2], s[nt][3]));
        }
        rmax0 *= scale; rmax1 *= scale;
        rmax0 = fmaxf(rmax0, __shfl_xor_sync(0xffffffffu, rmax0, 1));
        rmax0 = fmaxf(rmax0, __shfl_xor_sync(0xffffffffu, rmax0, 2));
        rmax1 = fmaxf(rmax1, __shfl_xor_sync(0xffffffffu, rmax1, 1));
        rmax1 = fmaxf(rmax1, __shfl_xor_sync(0xffffffffu, rmax1, 2));

        const float nm0 = fmaxf(mi0, rmax0);
        const float nm1 = fmaxf(mi1, rmax1);
        const float f0 = __expf(mi0 - nm0);
        const float f1 = __expf(mi1 - nm1);
        mi0 = nm0; mi1 = nm1;

        float rs0 = 0.f, rs1 = 0.f;
        #pragma unroll
        for (int nt = 0; nt < 8; nt++) {
            float p0 = __expf(s[nt][0] * scale - nm0);
            float p1 = __expf(s[nt][1] * scale - nm0);
            float p2 = __expf(s[nt][2] * scale - nm1);
            float p3 = __expf(s[nt][3] * scale - nm1);
            rs0 += p0 + p1;
            rs1 += p2 + p3;
            float2 w0, w1;
            w0.x = __uint_as_float(f2tf32(p0));
            w0.y = __uint_as_float(f2tf32(p1));
            w1.x = __uint_as_float(f2tf32(p2));
            w1.y = __uint_as_float(f2tf32(p3));
            *(float2*)(Ps + (wm + g)     * AP_PAD + nt*8 + 2*cc) = w0;
            *(float2*)(Ps + (wm + g + 8) * AP_PAD + nt*8 + 2*cc) = w1;
        }
        rs0 += __shfl_xor_sync(0xffffffffu, rs0, 1);
        rs0 += __shfl_xor_sync(0xffffffffu, rs0, 2);
        rs1 += __shfl_xor_sync(0xffffffffu, rs1, 1);
        rs1 += __shfl_xor_sync(0xffffffffu, rs1, 2);
        li0 = li0 * f0 + rs0;
        li1 = li1 * f1 + rs1;

        #pragma unroll
        for (int nt = 0; nt < 16; nt++) {
            o[nt][0] *= f0; o[nt][1] *= f0;
            o[nt][2] *= f1; o[nt][3] *= f1;
        }
        __syncwarp();

        // ---- O += P V^T (warp: 16 x 128) ----
        #pragma unroll
        for (int ks = 0; ks < 8; ks++) {
            uint32_t a[4];
            const float* ap = Ps + (wm + g) * AP_PAD + ks * 8 + cc;
            a[0] = __float_as_uint(ap[0]);
            a[1] = __float_as_uint(ap[8*AP_PAD]);
            a[2] = __float_as_uint(ap[4]);
            a[3] = __float_as_uint(ap[8*AP_PAD + 4]);
            #pragma unroll
            for (int nt = 0; nt < 16; nt++) {
                uint32_t b[2];
                const float* bp = Vt + (nt*8 + g) * AV_PAD + ks * 8 + cc;
                b[0] = __float_as_uint(bp[0]);
                b[1] = __float_as_uint(bp[4]);
                mma1688(o[nt], a, b);
            }
        }
        __syncthreads();
    }

    // ---- epilogue: out[b, s, hh*128 + d] = o / l ----
    const int b  = bh >> 4;
    const int hh = bh & 15;
    const float inv0 = 1.0f / li0;
    const float inv1 = 1.0f / li1;
    const int m0r = q0 + wm + g;
    #pragma unroll
    for (int nt = 0; nt < 16; nt++) {
        const int dd = nt*8 + 2*cc;
        float* op0 = out + ((size_t)(b * SEQLEN + m0r)) * HID + hh * HDIM + dd;
        float* op1 = out + ((size_t)(b * SEQLEN + m0r + 8)) * HID + hh * HDIM + dd;
        float2 r0, r1;
        r0.x = o[nt][0] * inv0; r0.y = o[nt][1] * inv0;
        r1.x = o[nt][2] * inv1; r1.y = o[nt][3] * inv1;
        *(float2*)op0 = r0;
        *(float2*)op1 = r1;
    }
}

// ---------------------------------------------------------------------------
extern "C" void kernel_launch(void* const* d_in, const int* in_sizes, int n_in,
                              void* d_out, int out_size)
{
    const float* X  = (const float*)d_in[0];
    const float* Wq = (const float*)d_in[1];
    const float* bq = (const float*)d_in[2];
    const float* Wk = (const float*)d_in[3];
    const float* bk = (const float*)d_in[4];
    const float* Wv = (const float*)d_in[5];
    const float* bv = (const float*)d_in[6];
    float* out = (float*)d_out;

    (void)cudaFuncSetAttribute(qkv_mma_kernel,
                               cudaFuncAttributeMaxDynamicSharedMemorySize,
                               GK_SMEM_DYN);
    (void)cudaFuncSetAttribute(attn_mma_kernel,
                               cudaFuncAttributeMaxDynamicSharedMemorySize,
                               ATT2_SMEM);

    dim3 gemm_grid(HID/128, MROWS/128, 3);              // 16 x 32 x 3
    qkv_mma_kernel<<<gemm_grid, 256, GK_SMEM_DYN>>>(X, Wq, bq, Wk, bk, Wv, bv);

    int rope_threads_total = 2 * NBH * SEQLEN * 64;     // 2^23
    rope_kernel<<<rope_threads_total / 256, 256>>>();

    dim3 attn_grid(SEQLEN/128, NBH);                    // 16 x 32
    attn_mma_kernel<<<attn_grid, 256, ATT2_SMEM>>>(out);
}